// round 1
// baseline (speedup 1.0000x reference)
#include <cuda_runtime.h>
#include <math.h>

#define HID   128
#define TQ    512
#define TK    512
#define QDIM  1024
#define MAXB  2
#define KTILE 128
#define EPSF  1e-5f

// ---------------- scratch (device globals; no allocation allowed) ----------------
__device__ __align__(16) float g_Qp [MAXB * TQ * HID];    // [b][q][h]
__device__ __align__(16) float g_KpT[MAXB * HID * TK];    // [b][j][k]  (transposed)
__device__ float g_sq [MAXB * TQ], g_sq2[MAXB * TQ];
__device__ float g_sk [MAXB * TK], g_sk2[MAXB * TK];
__device__ __align__(16) float g_W1u[HID * HID], g_W2u[HID * HID], g_W3u[HID * HID];
__device__ __align__(16) float g_W1v[HID * HID], g_W2v[HID * HID], g_W3v[HID * HID];
__device__ float g_Gu[HID], g_Bu[HID], g_Gv[HID], g_Bv[HID];

// ---------------- weight prep: Wi = diag(g_block) * W_block ----------------
__global__ void k_wprep(const float* __restrict__ g,
                        const float* __restrict__ Wu,
                        const float* __restrict__ Wv) {
    int j = blockIdx.x;      // 0..127
    int h = threadIdx.x;     // 0..127
    float g0 = g[j], g1 = g[HID + j], g2 = g[2 * HID + j];
    int i0 = j * HID + h, i1 = (HID + j) * HID + h, i2 = (2 * HID + j) * HID + h;
    g_W1u[i0] = g0 * Wu[i0]; g_W2u[i0] = g1 * Wu[i1]; g_W3u[i0] = g2 * Wu[i2];
    g_W1v[i0] = g0 * Wv[i0]; g_W2v[i0] = g1 * Wv[i1]; g_W3v[i0] = g2 * Wv[i2];
}

// Gu[h] = sum_c g_c Wu[c,h] ; Bu[h] = sum_c b_c Wu[c,h] + bu[h]  (same for v)
__global__ void k_gb(const float* __restrict__ g, const float* __restrict__ bln,
                     const float* __restrict__ Wu, const float* __restrict__ bu,
                     const float* __restrict__ Wv, const float* __restrict__ bv) {
    int h = threadIdx.x;
    float Gu = 0.f, Bu = 0.f, Gv = 0.f, Bv = 0.f;
    for (int c = 0; c < 3 * HID; c++) {
        float wu = Wu[c * HID + h], wv = Wv[c * HID + h];
        float gc = g[c], bc = bln[c];
        Gu = fmaf(gc, wu, Gu); Bu = fmaf(bc, wu, Bu);
        Gv = fmaf(gc, wv, Gv); Bv = fmaf(bc, wv, Bv);
    }
    g_Gu[h] = Gu; g_Bu[h] = Bu + bu[h];
    g_Gv[h] = Gv; g_Bv[h] = Bv + bv[h];
}

// ---------------- projection: Qp = Q@Wq (row-major), KpT = (K@Wk)^T ----------------
#define PROJ_ROWS 16
#define PROJ_DCHUNK 256
__global__ __launch_bounds__(128) void k_proj(const float* __restrict__ Q,
                                              const float* __restrict__ K,
                                              const float* __restrict__ Wq,
                                              const float* __restrict__ Wk,
                                              int B) {
    __shared__ __align__(16) float s[PROJ_ROWS][PROJ_DCHUNK];
    int nQ = B * TQ / PROJ_ROWS;
    bool isK = (int)blockIdx.x >= nQ;
    int blk = isK ? (blockIdx.x - nQ) : blockIdx.x;
    const float* X = isK ? K : Q;
    const float* W = isK ? Wk : Wq;
    int row0 = blk * PROJ_ROWS;
    int h = threadIdx.x;

    float acc[PROJ_ROWS];
#pragma unroll
    for (int r = 0; r < PROJ_ROWS; r++) acc[r] = 0.f;

    for (int d0 = 0; d0 < QDIM; d0 += PROJ_DCHUNK) {
        for (int i = threadIdx.x; i < PROJ_ROWS * (PROJ_DCHUNK / 4); i += 128) {
            int r  = i / (PROJ_DCHUNK / 4);
            int c4 = i % (PROJ_DCHUNK / 4);
            float4 v = *(const float4*)&X[(size_t)(row0 + r) * QDIM + d0 + c4 * 4];
            *(float4*)&s[r][c4 * 4] = v;
        }
        __syncthreads();
        for (int dd = 0; dd < PROJ_DCHUNK; dd += 4) {
            float w0 = W[(d0 + dd + 0) * HID + h];
            float w1 = W[(d0 + dd + 1) * HID + h];
            float w2 = W[(d0 + dd + 2) * HID + h];
            float w3 = W[(d0 + dd + 3) * HID + h];
#pragma unroll
            for (int r = 0; r < PROJ_ROWS; r++) {
                float4 sv = *(const float4*)&s[r][dd];
                acc[r] = fmaf(sv.x, w0, acc[r]);
                acc[r] = fmaf(sv.y, w1, acc[r]);
                acc[r] = fmaf(sv.z, w2, acc[r]);
                acc[r] = fmaf(sv.w, w3, acc[r]);
            }
        }
        __syncthreads();
    }
#pragma unroll
    for (int r = 0; r < PROJ_ROWS; r++) {
        int grow = row0 + r;
        if (isK) {
            int b = grow / TK, k = grow % TK;
            g_KpT[((size_t)b * HID + h) * TK + k] = acc[r];
        } else {
            g_Qp[(size_t)grow * HID + h] = acc[r];
        }
    }
}

// ---------------- per-row stats ----------------
__global__ void k_statsq(int B) {
    int warp = blockIdx.x * (blockDim.x >> 5) + (threadIdx.x >> 5);
    int lane = threadIdx.x & 31;
    if (warp >= B * TQ) return;
    float4 v = *(const float4*)&g_Qp[(size_t)warp * HID + lane * 4];
    float s  = v.x + v.y + v.z + v.w;
    float s2 = v.x * v.x + v.y * v.y + v.z * v.z + v.w * v.w;
#pragma unroll
    for (int o = 16; o; o >>= 1) {
        s  += __shfl_down_sync(0xffffffffu, s,  o);
        s2 += __shfl_down_sync(0xffffffffu, s2, o);
    }
    if (lane == 0) { g_sq[warp] = s; g_sq2[warp] = s2; }
}

__global__ void k_statsk(int B) {
    int b = blockIdx.x;
    int k = threadIdx.x;   // 0..511
    float s = 0.f, s2 = 0.f;
#pragma unroll 8
    for (int j = 0; j < HID; j++) {
        float v = g_KpT[((size_t)b * HID + j) * TK + k];
        s += v; s2 = fmaf(v, v, s2);
    }
    g_sk[b * TK + k] = s; g_sk2[b * TK + k] = s2;
}

// ---------------- main fused kernel: one CTA per (b,q) ----------------
struct SmemMain {
    float CmU[HID][HID];   // W2u + diag(q)*W3u
    float CmV[HID][HID];
    float KT [HID][KTILE]; // current K tile, [j][k]
    float qrow[HID], q2row[HID];
    float AqU[HID], AqV[HID];
    float Gu[HID], Bu[HID], Gv[HID], Bv[HID], Wo[HID];
    float rr[KTILE], rmu[KTILE];
};

__global__ __launch_bounds__(512, 1) void k_main(const float* __restrict__ Wo_g,
                                                 const float* __restrict__ bo_g,
                                                 float* __restrict__ out,
                                                 int B) {
    extern __shared__ char smraw[];
    SmemMain& sm = *reinterpret_cast<SmemMain*>(smraw);

    int tid = threadIdx.x;
    int bq  = blockIdx.x;
    int b   = bq / TQ;

    if (tid < HID) {
        float v = g_Qp[(size_t)bq * HID + tid];
        sm.qrow[tid]  = v;
        sm.q2row[tid] = v * v;
        sm.Gu[tid] = g_Gu[tid]; sm.Bu[tid] = g_Bu[tid];
        sm.Gv[tid] = g_Gv[tid]; sm.Bv[tid] = g_Bv[tid];
        sm.Wo[tid] = Wo_g[tid];
    }
    __syncthreads();

    // build Cm matrices (vectorized)
    for (int i = tid; i < HID * HID / 4; i += 512) {
        int j = i / (HID / 4);
        int c = i % (HID / 4);
        float qj = sm.qrow[j];
        float4 w2 = ((const float4*)g_W2u)[i];
        float4 w3 = ((const float4*)g_W3u)[i];
        float4 ou;
        ou.x = fmaf(qj, w3.x, w2.x); ou.y = fmaf(qj, w3.y, w2.y);
        ou.z = fmaf(qj, w3.z, w2.z); ou.w = fmaf(qj, w3.w, w2.w);
        *(float4*)&sm.CmU[j][c * 4] = ou;
        float4 x2 = ((const float4*)g_W2v)[i];
        float4 x3 = ((const float4*)g_W3v)[i];
        float4 ov;
        ov.x = fmaf(qj, x3.x, x2.x); ov.y = fmaf(qj, x3.y, x2.y);
        ov.z = fmaf(qj, x3.z, x2.z); ov.w = fmaf(qj, x3.w, x2.w);
        *(float4*)&sm.CmV[j][c * 4] = ov;
    }
    // Aq_u[h] = sum_j q_j W1u[j,h]   (q-part of LN-folded projection)
    {
        int part = tid >> 7, h = tid & 127;
        if (part == 0) {
            float a = 0.f;
#pragma unroll 8
            for (int j = 0; j < HID; j++) a = fmaf(sm.qrow[j], g_W1u[j * HID + h], a);
            sm.AqU[h] = a;
        } else if (part == 1) {
            float a = 0.f;
#pragma unroll 8
            for (int j = 0; j < HID; j++) a = fmaf(sm.qrow[j], g_W1v[j * HID + h], a);
            sm.AqV[h] = a;
        }
    }
    float sqv  = g_sq[bq];
    float sq2v = g_sq2[bq];
    float bo   = bo_g[0];
    __syncthreads();

    const int hc = tid & 31;     // h-column group (4 h's)
    const int kr = tid >> 5;     // k-row group (8 k's); warp == fixed kr
    const int hbase = hc * 4;
    const int kbase = kr * 8;
    const float inv384 = 1.0f / 384.0f;

    for (int t = 0; t < TK / KTILE; t++) {
        __syncthreads();   // previous tile fully consumed
        // load K tile [j][k]
        for (int i = tid; i < HID * KTILE / 4; i += 512) {
            int j = i >> 5, c = i & 31;
            *(float4*)&sm.KT[j][c * 4] =
                *(const float4*)&g_KpT[((size_t)b * HID + j) * TK + t * KTILE + c * 4];
        }
        __syncthreads();
        // per-k LN stats: mu, var from precomputed row sums + pair dots
        if (tid < KTILE) {
            int k = tid;
            float dqk = 0.f, d22 = 0.f;
#pragma unroll 8
            for (int j = 0; j < HID; j++) {
                float kv = sm.KT[j][k];
                dqk = fmaf(sm.qrow[j], kv, dqk);
                d22 = fmaf(sm.q2row[j], kv * kv, d22);
            }
            int kg = b * TK + t * KTILE + k;
            float mu  = (sqv  + g_sk[kg]  + dqk) * inv384;
            float ms  = (sq2v + g_sk2[kg] + d22) * inv384;
            float var = ms - mu * mu;
            float r   = rsqrtf(var + EPSF);
            sm.rr[k]  = r;
            sm.rmu[k] = r * mu;
        }
        __syncthreads();

        // ---- GEMM: acc[k][h] = Aq[h] + sum_j KT[j][k] * Cm[j][h] ----
        float accU[8][4], accV[8][4];
        {
            float4 au = *(const float4*)&sm.AqU[hbase];
            float4 av = *(const float4*)&sm.AqV[hbase];
#pragma unroll
            for (int i = 0; i < 8; i++) {
                accU[i][0] = au.x; accU[i][1] = au.y; accU[i][2] = au.z; accU[i][3] = au.w;
                accV[i][0] = av.x; accV[i][1] = av.y; accV[i][2] = av.z; accV[i][3] = av.w;
            }
        }
#pragma unroll 2
        for (int j = 0; j < HID; j++) {
            float4 a0 = *(const float4*)&sm.KT[j][kbase];
            float4 a1 = *(const float4*)&sm.KT[j][kbase + 4];
            float4 bu4 = *(const float4*)&sm.CmU[j][hbase];
            float4 bv4 = *(const float4*)&sm.CmV[j][hbase];
            float a[8]  = {a0.x, a0.y, a0.z, a0.w, a1.x, a1.y, a1.z, a1.w};
            float cu[4] = {bu4.x, bu4.y, bu4.z, bu4.w};
            float cv[4] = {bv4.x, bv4.y, bv4.z, bv4.w};
#pragma unroll
            for (int i = 0; i < 8; i++)
#pragma unroll
                for (int c = 0; c < 4; c++) {
                    accU[i][c] = fmaf(a[i], cu[c], accU[i][c]);
                    accV[i][c] = fmaf(a[i], cv[c], accV[i][c]);
                }
        }

        // ---- epilogue: LN fold + gelu + Wo dot + warp reduce over h ----
        float4 gu = *(const float4*)&sm.Gu[hbase];
        float4 bu4 = *(const float4*)&sm.Bu[hbase];
        float4 gv = *(const float4*)&sm.Gv[hbase];
        float4 bv4 = *(const float4*)&sm.Bv[hbase];
        float4 wo = *(const float4*)&sm.Wo[hbase];
        float guA[4] = {gu.x, gu.y, gu.z, gu.w};
        float buA[4] = {bu4.x, bu4.y, bu4.z, bu4.w};
        float gvA[4] = {gv.x, gv.y, gv.z, gv.w};
        float bvA[4] = {bv4.x, bv4.y, bv4.z, bv4.w};
        float woA[4] = {wo.x, wo.y, wo.z, wo.w};

#pragma unroll
        for (int i = 0; i < 8; i++) {
            float R  = sm.rr[kbase + i];
            float RM = sm.rmu[kbase + i];
            float p = 0.f;
#pragma unroll
            for (int c = 0; c < 4; c++) {
                float u = fmaf(R, accU[i][c], fmaf(-RM, guA[c], buA[c]));
                float v = fmaf(R, accV[i][c], fmaf(-RM, gvA[c], bvA[c]));
                float gl = 0.5f * v * (1.0f + erff(v * 0.70710678f));
                p = fmaf(u * gl, woA[c], p);
            }
#pragma unroll
            for (int o = 16; o; o >>= 1) p += __shfl_down_sync(0xffffffffu, p, o);
            if (hc == 0)
                out[(size_t)bq * TK + t * KTILE + kbase + i] = p + bo;
        }
    }
}

// ---------------- launch ----------------
extern "C" void kernel_launch(void* const* d_in, const int* in_sizes, int n_in,
                              void* d_out, int out_size) {
    const float* Q    = (const float*)d_in[0];
    const float* K    = (const float*)d_in[1];
    const float* Wq   = (const float*)d_in[2];
    const float* Wk   = (const float*)d_in[3];
    const float* ln_g = (const float*)d_in[4];
    const float* ln_b = (const float*)d_in[5];
    const float* Wu   = (const float*)d_in[6];
    const float* bu   = (const float*)d_in[7];
    const float* Wv   = (const float*)d_in[8];
    const float* bv   = (const float*)d_in[9];
    const float* Wo   = (const float*)d_in[10];
    const float* bo   = (const float*)d_in[11];

    int B = in_sizes[0] / (TQ * QDIM);
    if (B < 1) B = 1;
    if (B > MAXB) B = MAXB;

    cudaFuncSetAttribute(k_main, cudaFuncAttributeMaxDynamicSharedMemorySize,
                         (int)sizeof(SmemMain));

    k_wprep<<<HID, HID>>>(ln_g, Wu, Wv);
    k_gb<<<1, HID>>>(ln_g, ln_b, Wu, bu, Wv, bv);
    k_proj<<<2 * B * TQ / PROJ_ROWS, 128>>>(Q, K, Wq, Wk, B);
    k_statsq<<<(B * TQ + 7) / 8, 256>>>(B);
    k_statsk<<<B, TK>>>(B);
    k_main<<<B * TQ, 512, sizeof(SmemMain)>>>(Wo, bo, (float*)d_out, B);
}